// round 11
// baseline (speedup 1.0000x reference)
#include <cuda_runtime.h>

// FixBatchChebConv: B=8, N=50000, Cin=Cout=64, K=3, E=400000
#define BB    8
#define NN    50000
#define CC    64
#define KORD  3
#define EE    400000
#define FF    512           // BB*CC, features per node in transposed layout
#define FF4   (FF/4)

// ---------------- scratch (static device globals; no runtime allocation) ----
__device__ float g_xt[(size_t)NN * FF];   // x transposed  [N,512]
__device__ float g_t1[(size_t)NN * FF];   // tx1 = L @ x
__device__ int   g_deg[NN];
__device__ int   g_rowstart[NN];
__device__ int   g_fill[NN];
__device__ float g_dinv[NN];
__device__ int   g_col[EE];
__device__ float g_lap[EE];
__device__ int   g_total;
__device__ int   g_is64;

// ---------------- setup kernels --------------------------------------------
__global__ void k_init() {
    int n = blockIdx.x * blockDim.x + threadIdx.x;
    if (n < NN) { g_deg[n] = 0; g_fill[n] = 0; }
    if (n == 0) g_total = 0;
}

// Detect whether edge_index is int64 or int32 (JAX may silently downcast).
__global__ void k_detect(const void* ei) {
    const long long* p = (const long long*)ei;
    int lane = threadIdx.x;           // 64 threads
    long long v = p[lane];
    int ok = (v >= 0 && v < NN) ? 1 : 0;
    __syncthreads();
    unsigned m0 = __ballot_sync(0xffffffffu, ok);
    __shared__ unsigned warp_ok[2];
    if ((lane & 31) == 0) warp_ok[lane >> 5] = m0;
    __syncthreads();
    if (lane == 0) g_is64 = (warp_ok[0] == 0xffffffffu && warp_ok[1] == 0xffffffffu) ? 1 : 0;
}

__device__ __forceinline__ void load_edge(const void* ei, int e, int& r, int& c) {
    if (g_is64) {
        const long long* p = (const long long*)ei;
        r = (int)p[e]; c = (int)p[EE + e];
    } else {
        const int* p = (const int*)ei;
        r = p[e]; c = p[EE + e];
    }
}

__global__ void k_count(const void* ei) {
    int e = blockIdx.x * blockDim.x + threadIdx.x;
    if (e >= EE) return;
    int r, c; load_edge(ei, e, r, c);
    if (r != c) atomicAdd(&g_deg[r], 1);
}

__global__ void k_dinv() {
    int n = blockIdx.x * blockDim.x + threadIdx.x;
    if (n >= NN) return;
    int d = g_deg[n];
    g_dinv[n] = (d > 0) ? rsqrtf((float)d) : 0.0f;
}

// Assign each row a contiguous CSR segment (warp-aggregated atomic offset).
__global__ void k_assign() {
    int n = blockIdx.x * blockDim.x + threadIdx.x;
    int lane = threadIdx.x & 31;
    int d = (n < NN) ? g_deg[n] : 0;
    int incl = d;
    #pragma unroll
    for (int o = 1; o < 32; o <<= 1) {
        int y = __shfl_up_sync(0xffffffffu, incl, o);
        if (lane >= o) incl += y;
    }
    int tot = __shfl_sync(0xffffffffu, incl, 31);
    int base = 0;
    if (lane == 0) base = atomicAdd(&g_total, tot);
    base = __shfl_sync(0xffffffffu, base, 0);
    if (n < NN) g_rowstart[n] = base + incl - d;
}

__global__ void k_fill(const void* ei) {
    int e = blockIdx.x * blockDim.x + threadIdx.x;
    if (e >= EE) return;
    int r, c; load_edge(ei, e, r, c);
    if (r != c) {
        int pos = atomicAdd(&g_fill[r], 1);
        int idx = g_rowstart[r] + pos;
        g_col[idx] = c;
        g_lap[idx] = -g_dinv[r] * g_dinv[c];
    }
}

// xt[n][b*64+c] = x[b][n][c], float4-vectorized on both sides.
__global__ void k_transpose(const float* __restrict__ x) {
    int gid = blockIdx.x * blockDim.x + threadIdx.x;   // over NN*FF/4
    if (gid >= NN * FF4) return;
    int c4 = gid & 15;
    int b  = (gid >> 4) & 7;
    int n  = gid >> 7;
    float4 v = ((const float4*)x)[((size_t)b * NN + n) * 16 + c4];
    ((float4*)g_xt)[gid] = v;
}

// One warp per row: t1 = L @ xt  (pass 0 only; pass 1 is fused into the GEMM).
__global__ void k_spmm0() {
    int gw   = (blockIdx.x * blockDim.x + threadIdx.x) >> 5;
    int lane = threadIdx.x & 31;
    if (gw >= NN) return;

    int s = g_rowstart[gw];
    int e = s + g_deg[gw];

    float4 acc[4];
    #pragma unroll
    for (int q = 0; q < 4; q++) acc[q] = make_float4(0.f, 0.f, 0.f, 0.f);

    const float4* srcv = (const float4*)g_xt;
    for (int i = s; i < e; i++) {
        int   c = g_col[i];
        float w = g_lap[i];
        size_t b0 = (size_t)c * FF4 + lane;
        #pragma unroll
        for (int q = 0; q < 4; q++) {
            float4 v = __ldg(&srcv[b0 + q * 32]);
            acc[q].x += w * v.x; acc[q].y += w * v.y;
            acc[q].z += w * v.z; acc[q].w += w * v.w;
        }
    }

    size_t o0 = (size_t)gw * FF4 + lane;
    float4* dstv = (float4*)g_t1;
    #pragma unroll
    for (int q = 0; q < 4; q++) dstv[o0 + q * 32] = acc[q];
}

// ---------------- packed f32x2 helpers --------------------------------------
__device__ __forceinline__ unsigned long long pack2(float f) {
    unsigned long long d;
    unsigned u = __float_as_uint(f);
    asm("mov.b64 %0, {%1, %1};" : "=l"(d) : "r"(u));
    return d;
}
__device__ __forceinline__ void unpack2(unsigned long long v, float& lo, float& hi) {
    unsigned a, b;
    asm("mov.b64 {%0, %1}, %2;" : "=r"(a), "=r"(b) : "l"(v));
    lo = __uint_as_float(a); hi = __uint_as_float(b);
}
#define FMA2(acc, a, b) asm("fma.rn.f32x2 %0, %1, %2, %0;" : "+l"(acc) : "l"(a), "l"(b))

// Fused SpMM(pass1) + epilogue GEMM (packed f32x2 FFMA2):
//   out[b,n,co] = bias[co] + sum_ci ( xt*W0 + t1*W1 + t2*W2 )
//   with t2 = 2*(L @ t1) - xt computed ON THE FLY into the A tile.
// Block tile: 256 rows (32 nodes x 8 batches) x 64 cols; K=192 in 6 chunks of 32.
// Taps 0/1 stage linearly; tap-2 chunks stage by edge gather. Each gather lane
// covers TWO float4s (fo, fo+4) so the full 32-ci chunk is written (R7 bug fix).
#define KC    32
#define AST   258            // even (LDS.64 pairs); gather STS conflict-free
__global__ void __launch_bounds__(256, 2) k_fused(const float* __restrict__ wgt,
                                                   const float* __restrict__ bias,
                                                   float* __restrict__ out) {
    __shared__ float As[KC * AST];   // [k][m], m = dn*8+b     (33024 B)
    __shared__ float Ws[KC * 64];    // [k][co]                ( 8192 B)

    int tid = threadIdx.x;
    int tx  = tid & 31;
    int wp  = tid >> 5;              // col group: cols wp*8 .. wp*8+7
    int n0  = blockIdx.x * 32;

    int s_ci = tid & 31;             // linear staging: k within chunk
    int s_b  = tid >> 5;             // linear staging: batch

    int g_b  = tx >> 2;              // gather staging: batch (0..7)
    int g_c4 = tx & 3;               // gather staging: first float4 idx (0..3)

    unsigned long long acc[4][8];
    #pragma unroll
    for (int i = 0; i < 4; i++)
        #pragma unroll
        for (int j = 0; j < 8; j++) acc[i][j] = 0ULL;

    #pragma unroll 1
    for (int kc = 0; kc < 6; kc++) {
        int t    = kc >> 1;
        int koff = (kc & 1) * 32;

        if (kc) __syncthreads();

        // stage W chunk (linear copy)
        #pragma unroll
        for (int i = 0; i < 8; i++) {
            int j = tid + i * 256;
            Ws[j] = __ldg(&wgt[t * 4096 + koff * 64 + j]);
        }

        if (t < 2) {
            // linear A stage: As[ci][dn*8+b] = src[(n0+dn)*512 + b*64+koff+ci]
            const float* src = (t == 0) ? g_xt : g_t1;
            #pragma unroll
            for (int dn = 0; dn < 32; dn++) {
                int n = n0 + dn;
                if (n >= NN) n = NN - 1;
                As[s_ci * AST + dn * 8 + s_b] =
                    __ldg(&src[(size_t)n * FF + s_b * 64 + koff + s_ci]);
            }
        } else {
            // gather A stage: t2 chunk = 2*(L @ t1) - xt.
            // Warp wp handles nodes dn = wp*4..wp*4+3. Each lane (g_b, g_c4)
            // accumulates TWO float4s (fo, fo+4): 32 lanes x 8 floats
            // = 256 floats = the full 8-batch x 32-ci chunk per node.
            const float4* t1v = (const float4*)g_t1;
            const float4* xtv = (const float4*)g_xt;
            int fo = (koff >> 2) + g_c4;          // float4 offset within row
            #pragma unroll
            for (int dn4 = 0; dn4 < 4; dn4++) {
                int dn = wp * 4 + dn4;
                int n  = n0 + dn;
                if (n >= NN) n = NN - 1;
                int s = g_rowstart[n];
                int e = s + g_deg[n];
                float4 a0 = make_float4(0.f, 0.f, 0.f, 0.f);
                float4 a1 = make_float4(0.f, 0.f, 0.f, 0.f);
                for (int i = s; i < e; i++) {
                    int   c = g_col[i];
                    float w = g_lap[i];
                    size_t bse = (size_t)c * FF4 + g_b * 16 + fo;
                    float4 v0 = __ldg(&t1v[bse]);
                    float4 v1 = __ldg(&t1v[bse + 4]);
                    a0.x += w * v0.x; a0.y += w * v0.y;
                    a0.z += w * v0.z; a0.w += w * v0.w;
                    a1.x += w * v1.x; a1.y += w * v1.y;
                    a1.z += w * v1.z; a1.w += w * v1.w;
                }
                size_t xb = (size_t)n * FF4 + g_b * 16 + fo;
                float4 x0 = __ldg(&xtv[xb]);
                float4 x1 = __ldg(&xtv[xb + 4]);
                // rows g_c4*4+{0..3}: banks (g_c4*8+g_b) distinct over lanes
                float* d0 = As + (g_c4 * 4) * AST + dn * 8 + g_b;
                d0[0]       = 2.f * a0.x - x0.x;
                d0[AST]     = 2.f * a0.y - x0.y;
                d0[2 * AST] = 2.f * a0.z - x0.z;
                d0[3 * AST] = 2.f * a0.w - x0.w;
                // rows (g_c4+4)*4+{0..3}
                float* d1 = As + ((g_c4 + 4) * 4) * AST + dn * 8 + g_b;
                d1[0]       = 2.f * a1.x - x1.x;
                d1[AST]     = 2.f * a1.y - x1.y;
                d1[2 * AST] = 2.f * a1.z - x1.z;
                d1[3 * AST] = 2.f * a1.w - x1.w;
            }
        }
        __syncthreads();

        #pragma unroll 4
        for (int kk = 0; kk < KC; kk++) {
            const float4* wrow = (const float4*)(Ws + kk * 64 + wp * 8);
            float4 wa = wrow[0], wb = wrow[1];
            unsigned long long wd[8];
            wd[0] = pack2(wa.x); wd[1] = pack2(wa.y);
            wd[2] = pack2(wa.z); wd[3] = pack2(wa.w);
            wd[4] = pack2(wb.x); wd[5] = pack2(wb.y);
            wd[6] = pack2(wb.z); wd[7] = pack2(wb.w);
            #pragma unroll
            for (int jp = 0; jp < 4; jp++) {
                unsigned long long ap =
                    *(const unsigned long long*)(As + kk * AST + jp * 64 + 2 * tx);
                #pragma unroll
                for (int c = 0; c < 8; c++) FMA2(acc[jp][c], ap, wd[c]);
            }
        }
    }

    // epilogue: bias + store, rows guarded for the partial last block
    float bvs[8];
    {
        float4 b0 = *(const float4*)(bias + wp * 8);
        float4 b1 = *(const float4*)(bias + wp * 8 + 4);
        bvs[0]=b0.x; bvs[1]=b0.y; bvs[2]=b0.z; bvs[3]=b0.w;
        bvs[4]=b1.x; bvs[5]=b1.y; bvs[6]=b1.z; bvs[7]=b1.w;
    }
    #pragma unroll
    for (int jp = 0; jp < 4; jp++) {
        int m0 = jp * 64 + 2 * tx;       // pair shares dn; batches b and b+1
        int dn = m0 >> 3;
        int n  = n0 + dn;
        if (n >= NN) continue;
        int b  = m0 & 7;
        float lo[8], hi[8];
        #pragma unroll
        for (int c = 0; c < 8; c++) unpack2(acc[jp][c], lo[c], hi[c]);
        float4 o0, o1;
        o0.x = lo[0]+bvs[0]; o0.y = lo[1]+bvs[1]; o0.z = lo[2]+bvs[2]; o0.w = lo[3]+bvs[3];
        o1.x = lo[4]+bvs[4]; o1.y = lo[5]+bvs[5]; o1.z = lo[6]+bvs[6]; o1.w = lo[7]+bvs[7];
        float* p0 = out + ((size_t)b * NN + n) * 64 + wp * 8;
        *(float4*)p0 = o0; *(float4*)(p0 + 4) = o1;
        o0.x = hi[0]+bvs[0]; o0.y = hi[1]+bvs[1]; o0.z = hi[2]+bvs[2]; o0.w = hi[3]+bvs[3];
        o1.x = hi[4]+bvs[4]; o1.y = hi[5]+bvs[5]; o1.z = hi[6]+bvs[6]; o1.w = hi[7]+bvs[7];
        float* p1 = out + ((size_t)(b + 1) * NN + n) * 64 + wp * 8;
        *(float4*)p1 = o0; *(float4*)(p1 + 4) = o1;
    }
}

// ---------------- launch ----------------------------------------------------
extern "C" void kernel_launch(void* const* d_in, const int* in_sizes, int n_in,
                              void* d_out, int out_size) {
    const float* x    = (const float*)d_in[0];   // [8, 50000, 64] f32
    const float* wgt  = (const float*)d_in[1];   // [3, 64, 64]    f32
    const float* bias = (const float*)d_in[2];   // [64]           f32
    const void*  ei   = d_in[3];                 // [2, 400000] int64 or int32
    float* out = (float*)d_out;                  // [8, 50000, 64] f32

    k_init<<<(NN + 255) / 256, 256>>>();
    k_detect<<<1, 64>>>(ei);
    k_count<<<(EE + 255) / 256, 256>>>(ei);
    k_dinv<<<(NN + 255) / 256, 256>>>();
    k_assign<<<(NN + 255) / 256, 256>>>();
    k_fill<<<(EE + 255) / 256, 256>>>(ei);
    k_transpose<<<(NN * FF4 + 255) / 256, 256>>>(x);
    k_spmm0<<<(NN * 32 + 255) / 256, 256>>>();
    k_fused<<<(NN + 31) / 32, 256>>>(wgt, bias, out);
}

// round 12
// speedup vs baseline: 1.0535x; 1.0535x over previous
#include <cuda_runtime.h>

// FixBatchChebConv: B=8, N=50000, Cin=Cout=64, K=3, E=400000
#define BB    8
#define NN    50000
#define CC    64
#define KORD  3
#define EE    400000
#define FF    512           // BB*CC, features per node in transposed layout
#define FF4   (FF/4)

// ---------------- scratch (static device globals; no runtime allocation) ----
// NOTE: x is consumed in its native layout; "xt[n][b*64+c]" == x[(b*NN+n)*64+c].
__device__ float g_t1[(size_t)NN * FF];   // tx1 = L @ x   (transposed [n][512])
__device__ float g_t2[(size_t)NN * FF];   // tx2 = 2 L tx1 - x (transposed)
__device__ int   g_deg[NN];
__device__ int   g_rowstart[NN];
__device__ int   g_fill[NN];
__device__ float g_dinv[NN];
__device__ int   g_col[EE];
__device__ float g_lap[EE];
__device__ int   g_total;
__device__ int   g_is64;

// ---------------- setup kernels (fused) -------------------------------------
// init counters + detect int64-vs-int32 edge_index (JAX may silently downcast:
// int32 data read as int64 packs two random indices -> >= NN almost surely).
__global__ void k_setup1(const void* ei) {
    int n = blockIdx.x * blockDim.x + threadIdx.x;
    if (n < NN) { g_deg[n] = 0; g_fill[n] = 0; }
    if (n == 0) g_total = 0;
    if (blockIdx.x == 0 && threadIdx.x < 64) {
        const long long* p = (const long long*)ei;
        long long v = p[threadIdx.x];
        int ok = (v >= 0 && v < NN) ? 1 : 0;
        unsigned m0 = __ballot_sync(0xffffffffu, ok);
        __shared__ unsigned warp_ok[2];
        if ((threadIdx.x & 31) == 0) warp_ok[threadIdx.x >> 5] = m0;
        __syncwarp();
        if (threadIdx.x == 32) {   // runs after warp1's write in its own warp
            // combine: warp 0's result via shared, warp 1's via m0
        }
        __syncthreads();
        if (threadIdx.x == 0)
            g_is64 = (warp_ok[0] == 0xffffffffu && warp_ok[1] == 0xffffffffu) ? 1 : 0;
    }
}

__device__ __forceinline__ void load_edge(const void* ei, int e, int& r, int& c) {
    if (g_is64) {
        const long long* p = (const long long*)ei;
        r = (int)p[e]; c = (int)p[EE + e];
    } else {
        const int* p = (const int*)ei;
        r = p[e]; c = p[EE + e];
    }
}

__global__ void k_count(const void* ei) {
    int e = blockIdx.x * blockDim.x + threadIdx.x;
    if (e >= EE) return;
    int r, c; load_edge(ei, e, r, c);
    if (r != c) atomicAdd(&g_deg[r], 1);
}

// dinv + CSR segment assignment (warp-aggregated atomic offset), fused.
__global__ void k_setup2() {
    int n = blockIdx.x * blockDim.x + threadIdx.x;
    int lane = threadIdx.x & 31;
    int d = (n < NN) ? g_deg[n] : 0;
    if (n < NN) g_dinv[n] = (d > 0) ? rsqrtf((float)d) : 0.0f;
    int incl = d;
    #pragma unroll
    for (int o = 1; o < 32; o <<= 1) {
        int y = __shfl_up_sync(0xffffffffu, incl, o);
        if (lane >= o) incl += y;
    }
    int tot = __shfl_sync(0xffffffffu, incl, 31);
    int base = 0;
    if (lane == 0) base = atomicAdd(&g_total, tot);
    base = __shfl_sync(0xffffffffu, base, 0);
    if (n < NN) g_rowstart[n] = base + incl - d;
}

__global__ void k_fill(const void* ei) {
    int e = blockIdx.x * blockDim.x + threadIdx.x;
    if (e >= EE) return;
    int r, c; load_edge(ei, e, r, c);
    if (r != c) {
        int pos = atomicAdd(&g_fill[r], 1);
        int idx = g_rowstart[r] + pos;
        g_col[idx] = c;
        g_lap[idx] = -g_dinv[r] * g_dinv[c];
    }
}

// One warp per row: t1 = L @ x  (x read in native [b][n][c] layout).
// Feature f = lane4*4.. as float4 q: b = (lane>>4)+q*2, c4 = lane&15.
__global__ void k_spmm0(const float* __restrict__ x) {
    int gw   = (blockIdx.x * blockDim.x + threadIdx.x) >> 5;
    int lane = threadIdx.x & 31;
    if (gw >= NN) return;

    int s = g_rowstart[gw];
    int e = s + g_deg[gw];

    int c4 = lane & 15;
    int b0 = lane >> 4;

    float4 acc[4];
    #pragma unroll
    for (int q = 0; q < 4; q++) acc[q] = make_float4(0.f, 0.f, 0.f, 0.f);

    const float4* xv = (const float4*)x;
    for (int i = s; i < e; i++) {
        int   c = g_col[i];
        float w = g_lap[i];
        #pragma unroll
        for (int q = 0; q < 4; q++) {
            int b = b0 + q * 2;
            float4 v = __ldg(&xv[((size_t)b * NN + c) * 16 + c4]);
            acc[q].x += w * v.x; acc[q].y += w * v.y;
            acc[q].z += w * v.z; acc[q].w += w * v.w;
        }
    }

    // store transposed: t1[gw][ (b0+q*2)*64 + c4*4 .. ]
    float4* dstv = (float4*)g_t1;
    size_t o0 = (size_t)gw * FF4 + lane;   // lane = b0*16+c4 -> same mapping
    #pragma unroll
    for (int q = 0; q < 4; q++) dstv[o0 + q * 32] = acc[q];
}

// One warp per row: t2 = 2*(L @ t1) - x. t1 reads are 2KB contiguous/edge.
__global__ void k_spmm1(const float* __restrict__ x) {
    int gw   = (blockIdx.x * blockDim.x + threadIdx.x) >> 5;
    int lane = threadIdx.x & 31;
    if (gw >= NN) return;

    int s = g_rowstart[gw];
    int e = s + g_deg[gw];

    float4 acc[4];
    #pragma unroll
    for (int q = 0; q < 4; q++) acc[q] = make_float4(0.f, 0.f, 0.f, 0.f);

    const float4* srcv = (const float4*)g_t1;
    for (int i = s; i < e; i++) {
        int   c = g_col[i];
        float w = g_lap[i];
        size_t b0 = (size_t)c * FF4 + lane;
        #pragma unroll
        for (int q = 0; q < 4; q++) {
            float4 v = __ldg(&srcv[b0 + q * 32]);
            acc[q].x += w * v.x; acc[q].y += w * v.y;
            acc[q].z += w * v.z; acc[q].w += w * v.w;
        }
    }

    int c4 = lane & 15;
    int bb = lane >> 4;
    const float4* xv = (const float4*)x;
    float4* dstv = (float4*)g_t2;
    size_t o0 = (size_t)gw * FF4 + lane;
    #pragma unroll
    for (int q = 0; q < 4; q++) {
        float4 c0 = __ldg(&xv[((size_t)(bb + q * 2) * NN + gw) * 16 + c4]);
        float4 o;
        o.x = 2.0f * acc[q].x - c0.x;
        o.y = 2.0f * acc[q].y - c0.y;
        o.z = 2.0f * acc[q].z - c0.z;
        o.w = 2.0f * acc[q].w - c0.w;
        dstv[o0 + q * 32] = o;
    }
}

// ---------------- packed f32x2 helpers --------------------------------------
__device__ __forceinline__ unsigned long long pack2(float f) {
    unsigned long long d;
    unsigned u = __float_as_uint(f);
    asm("mov.b64 %0, {%1, %1};" : "=l"(d) : "r"(u));
    return d;
}
__device__ __forceinline__ void unpack2(unsigned long long v, float& lo, float& hi) {
    unsigned a, b;
    asm("mov.b64 {%0, %1}, %2;" : "=r"(a), "=r"(b) : "l"(v));
    lo = __uint_as_float(a); hi = __uint_as_float(b);
}
#define FMA2(acc, a, b) asm("fma.rn.f32x2 %0, %1, %2, %0;" : "+l"(acc) : "l"(a), "l"(b))

// Epilogue GEMM (packed f32x2 FFMA2), split structure (R5 proven):
//   out[b,n,co] = bias[co] + sum_t sum_ci A_t[n][b,ci] * W[t][ci][co]
// tap 0 reads x natively; taps 1/2 read the transposed t1/t2 buffers.
#define KC    32
#define AST   258            // even (LDS.64 pairs)
__global__ void __launch_bounds__(256, 2) k_gemm2(const float* __restrict__ x,
                                                   const float* __restrict__ wgt,
                                                   const float* __restrict__ bias,
                                                   float* __restrict__ out) {
    __shared__ float As[KC * AST];   // [k][m], m = dn*8+b     (33024 B)
    __shared__ float Ws[KC * 64];    // [k][co]                ( 8192 B)

    int tid = threadIdx.x;
    int tx  = tid & 31;
    int wp  = tid >> 5;              // col group: cols wp*8 .. wp*8+7
    int n0  = blockIdx.x * 32;

    int s_ci = tid & 31;             // staging: k within chunk
    int s_b  = tid >> 5;             // staging: batch

    unsigned long long acc[4][8];
    #pragma unroll
    for (int i = 0; i < 4; i++)
        #pragma unroll
        for (int j = 0; j < 8; j++) acc[i][j] = 0ULL;

    #pragma unroll 1
    for (int kc = 0; kc < 6; kc++) {
        int t    = kc >> 1;
        int koff = (kc & 1) * 32;

        if (kc) __syncthreads();

        // stage W chunk (linear copy)
        #pragma unroll
        for (int i = 0; i < 8; i++) {
            int j = tid + i * 256;
            Ws[j] = __ldg(&wgt[t * 4096 + koff * 64 + j]);
        }
        // stage A chunk: As[ci][dn*8+b]
        if (t == 0) {
            #pragma unroll
            for (int dn = 0; dn < 32; dn++) {
                int n = n0 + dn;
                if (n >= NN) n = NN - 1;
                As[s_ci * AST + dn * 8 + s_b] =
                    __ldg(&x[((size_t)s_b * NN + n) * 64 + koff + s_ci]);
            }
        } else {
            const float* src = (t == 1) ? g_t1 : g_t2;
            #pragma unroll
            for (int dn = 0; dn < 32; dn++) {
                int n = n0 + dn;
                if (n >= NN) n = NN - 1;
                As[s_ci * AST + dn * 8 + s_b] =
                    __ldg(&src[(size_t)n * FF + s_b * 64 + koff + s_ci]);
            }
        }
        __syncthreads();

        #pragma unroll 4
        for (int kk = 0; kk < KC; kk++) {
            const float4* wrow = (const float4*)(Ws + kk * 64 + wp * 8);
            float4 wa = wrow[0], wb = wrow[1];
            unsigned long long wd[8];
            wd[0] = pack2(wa.x); wd[1] = pack2(wa.y);
            wd[2] = pack2(wa.z); wd[3] = pack2(wa.w);
            wd[4] = pack2(wb.x); wd[5] = pack2(wb.y);
            wd[6] = pack2(wb.z); wd[7] = pack2(wb.w);
            #pragma unroll
            for (int jp = 0; jp < 4; jp++) {
                unsigned long long ap =
                    *(const unsigned long long*)(As + kk * AST + jp * 64 + 2 * tx);
                #pragma unroll
                for (int c = 0; c < 8; c++) FMA2(acc[jp][c], ap, wd[c]);
            }
        }
    }

    // epilogue: bias + store, rows guarded for the partial last block
    float bvs[8];
    {
        float4 b0 = *(const float4*)(bias + wp * 8);
        float4 b1 = *(const float4*)(bias + wp * 8 + 4);
        bvs[0]=b0.x; bvs[1]=b0.y; bvs[2]=b0.z; bvs[3]=b0.w;
        bvs[4]=b1.x; bvs[5]=b1.y; bvs[6]=b1.z; bvs[7]=b1.w;
    }
    #pragma unroll
    for (int jp = 0; jp < 4; jp++) {
        int m0 = jp * 64 + 2 * tx;       // pair shares dn; batches b and b+1
        int dn = m0 >> 3;
        int n  = n0 + dn;
        if (n >= NN) continue;
        int b  = m0 & 7;
        float lo[8], hi[8];
        #pragma unroll
        for (int c = 0; c < 8; c++) unpack2(acc[jp][c], lo[c], hi[c]);
        float4 o0, o1;
        o0.x = lo[0]+bvs[0]; o0.y = lo[1]+bvs[1]; o0.z = lo[2]+bvs[2]; o0.w = lo[3]+bvs[3];
        o1.x = lo[4]+bvs[4]; o1.y = lo[5]+bvs[5]; o1.z = lo[6]+bvs[6]; o1.w = lo[7]+bvs[7];
        float* p0 = out + ((size_t)b * NN + n) * 64 + wp * 8;
        *(float4*)p0 = o0; *(float4*)(p0 + 4) = o1;
        o0.x = hi[0]+bvs[0]; o0.y = hi[1]+bvs[1]; o0.z = hi[2]+bvs[2]; o0.w = hi[3]+bvs[3];
        o1.x = hi[4]+bvs[4]; o1.y = hi[5]+bvs[5]; o1.z = hi[6]+bvs[6]; o1.w = hi[7]+bvs[7];
        float* p1 = out + ((size_t)(b + 1) * NN + n) * 64 + wp * 8;
        *(float4*)p1 = o0; *(float4*)(p1 + 4) = o1;
    }
}

// ---------------- launch ----------------------------------------------------
extern "C" void kernel_launch(void* const* d_in, const int* in_sizes, int n_in,
                              void* d_out, int out_size) {
    const float* x    = (const float*)d_in[0];   // [8, 50000, 64] f32
    const float* wgt  = (const float*)d_in[1];   // [3, 64, 64]    f32
    const float* bias = (const float*)d_in[2];   // [64]           f32
    const void*  ei   = d_in[3];                 // [2, 400000] int64 or int32
    float* out = (float*)d_out;                  // [8, 50000, 64] f32

    k_setup1<<<(NN + 255) / 256, 256>>>(ei);
    k_count<<<(EE + 255) / 256, 256>>>(ei);
    k_setup2<<<(NN + 255) / 256, 256>>>();
    k_fill<<<(EE + 255) / 256, 256>>>(ei);
    k_spmm0<<<(NN * 32 + 255) / 256, 256>>>(x);
    k_spmm1<<<(NN * 32 + 255) / 256, 256>>>(x);
    k_gemm2<<<(NN + 31) / 32, 256>>>(x, wgt, bias, out);
}

// round 14
// speedup vs baseline: 1.0780x; 1.0232x over previous
#include <cuda_runtime.h>
#include <cstdint>

// FixBatchChebConv: B=8, N=50000, Cin=Cout=64, K=3, E=400000
#define BB    8
#define NN    50000
#define EE    400000
#define FF    512           // BB*64, features per node in transposed layout
#define FF4   (FF/4)

// ---------------- scratch (static device globals; no runtime allocation) ----
__device__ float g_t1[(size_t)NN * FF];   // tx1 = L @ x    (transposed [n][512])
__device__ float g_u [(size_t)NN * FF];   // u   = L @ tx1  (transposed; t2 = 2u - x folded into W)
__device__ float g_wt[12288];             // folded weights: [W0-W2 | W1 | 2*W2], [t][ci][co]
__device__ int   g_deg[NN];
__device__ int   g_rowstart[NN];
__device__ int   g_fill[NN];
__device__ float g_dinv[NN];
__device__ int   g_col[EE];
__device__ float g_lap[EE];
__device__ int   g_total;
__device__ int   g_is64;

// ---------------- setup kernels ---------------------------------------------
// init counters + weight folding + int64/int32 edge_index detection
// (int32 data read as int64 packs two random indices -> >= NN almost surely).
__global__ void k_setup1(const void* ei, const float* __restrict__ wgt) {
    int n = blockIdx.x * blockDim.x + threadIdx.x;
    if (n < NN) { g_deg[n] = 0; g_fill[n] = 0; }
    if (n == 0) g_total = 0;
    if (n < 12288) {
        int t = n >> 12;                 // 0..2
        float w = wgt[n];
        if (t == 0)      w = w - wgt[n + 8192];   // W0 - W2
        else if (t == 2) w = 2.0f * w;            // 2*W2
        g_wt[n] = w;
    }
    if (blockIdx.x == 0 && threadIdx.x < 64) {
        const long long* p = (const long long*)ei;
        long long v = p[threadIdx.x];
        int ok = (v >= 0 && v < NN) ? 1 : 0;
        unsigned m0 = __ballot_sync(0xffffffffu, ok);
        __shared__ unsigned warp_ok[2];
        if ((threadIdx.x & 31) == 0) warp_ok[threadIdx.x >> 5] = m0;
        __syncthreads();
        if (threadIdx.x == 0)
            g_is64 = (warp_ok[0] == 0xffffffffu && warp_ok[1] == 0xffffffffu) ? 1 : 0;
    }
}

__device__ __forceinline__ void load_edge(const void* ei, int e, int& r, int& c) {
    if (g_is64) {
        const long long* p = (const long long*)ei;
        r = (int)p[e]; c = (int)p[EE + e];
    } else {
        const int* p = (const int*)ei;
        r = p[e]; c = p[EE + e];
    }
}

__global__ void k_count(const void* ei) {
    int e = blockIdx.x * blockDim.x + threadIdx.x;
    if (e >= EE) return;
    int r, c; load_edge(ei, e, r, c);
    if (r != c) atomicAdd(&g_deg[r], 1);
}

// dinv + CSR segment assignment (warp-aggregated atomic offset).
__global__ void k_setup2() {
    int n = blockIdx.x * blockDim.x + threadIdx.x;
    int lane = threadIdx.x & 31;
    int d = (n < NN) ? g_deg[n] : 0;
    if (n < NN) g_dinv[n] = (d > 0) ? rsqrtf((float)d) : 0.0f;
    int incl = d;
    #pragma unroll
    for (int o = 1; o < 32; o <<= 1) {
        int y = __shfl_up_sync(0xffffffffu, incl, o);
        if (lane >= o) incl += y;
    }
    int tot = __shfl_sync(0xffffffffu, incl, 31);
    int base = 0;
    if (lane == 0) base = atomicAdd(&g_total, tot);
    base = __shfl_sync(0xffffffffu, base, 0);
    if (n < NN) g_rowstart[n] = base + incl - d;
}

__global__ void k_fill(const void* ei) {
    int e = blockIdx.x * blockDim.x + threadIdx.x;
    if (e >= EE) return;
    int r, c; load_edge(ei, e, r, c);
    if (r != c) {
        int pos = atomicAdd(&g_fill[r], 1);
        int idx = g_rowstart[r] + pos;
        g_col[idx] = c;
        g_lap[idx] = -g_dinv[r] * g_dinv[c];
    }
}

// One warp per row: t1 = L @ x  (x read in native [b][n][c] layout).
__global__ void k_spmm0(const float* __restrict__ x) {
    int gw   = (blockIdx.x * blockDim.x + threadIdx.x) >> 5;
    int lane = threadIdx.x & 31;
    if (gw >= NN) return;
    int s = g_rowstart[gw];
    int e = s + g_deg[gw];
    int c4 = lane & 15;
    int b0 = lane >> 4;
    float4 acc[4];
    #pragma unroll
    for (int q = 0; q < 4; q++) acc[q] = make_float4(0.f, 0.f, 0.f, 0.f);
    const float4* xv = (const float4*)x;
    for (int i = s; i < e; i++) {
        int   c = g_col[i];
        float w = g_lap[i];
        #pragma unroll
        for (int q = 0; q < 4; q++) {
            float4 v = __ldg(&xv[((size_t)(b0 + q * 2) * NN + c) * 16 + c4]);
            acc[q].x += w * v.x; acc[q].y += w * v.y;
            acc[q].z += w * v.z; acc[q].w += w * v.w;
        }
    }
    float4* dstv = (float4*)g_t1;
    size_t o0 = (size_t)gw * FF4 + lane;
    #pragma unroll
    for (int q = 0; q < 4; q++) dstv[o0 + q * 32] = acc[q];
}

// One warp per row: u = L @ t1 (raw gather; 2u - x folded into weights).
__global__ void k_spmm1() {
    int gw   = (blockIdx.x * blockDim.x + threadIdx.x) >> 5;
    int lane = threadIdx.x & 31;
    if (gw >= NN) return;
    int s = g_rowstart[gw];
    int e = s + g_deg[gw];
    float4 acc[4];
    #pragma unroll
    for (int q = 0; q < 4; q++) acc[q] = make_float4(0.f, 0.f, 0.f, 0.f);
    const float4* srcv = (const float4*)g_t1;
    for (int i = s; i < e; i++) {
        int   c = g_col[i];
        float w = g_lap[i];
        size_t b0 = (size_t)c * FF4 + lane;
        #pragma unroll
        for (int q = 0; q < 4; q++) {
            float4 v = __ldg(&srcv[b0 + q * 32]);
            acc[q].x += w * v.x; acc[q].y += w * v.y;
            acc[q].z += w * v.z; acc[q].w += w * v.w;
        }
    }
    float4* dstv = (float4*)g_u;
    size_t o0 = (size_t)gw * FF4 + lane;
    #pragma unroll
    for (int q = 0; q < 4; q++) dstv[o0 + q * 32] = acc[q];
}

// ---------------- packed f32x2 helpers --------------------------------------
__device__ __forceinline__ unsigned long long pack2(float f) {
    unsigned long long d;
    unsigned u = __float_as_uint(f);
    asm("mov.b64 %0, {%1, %1};" : "=l"(d) : "r"(u));
    return d;
}
__device__ __forceinline__ void unpack2(unsigned long long v, float& lo, float& hi) {
    unsigned a, b;
    asm("mov.b64 {%0, %1}, %2;" : "=r"(a), "=r"(b) : "l"(v));
    lo = __uint_as_float(a); hi = __uint_as_float(b);
}
#define FMA2(acc, a, b) asm("fma.rn.f32x2 %0, %1, %2, %0;" : "+l"(acc) : "l"(a), "l"(b))

// Software-pipelined FFMA2 GEMM:
//   out[b,n,co] = bias[co] + sum_t sum_ci A_t[n][b,ci] * Wt'[ci][co]
//   taps: A_0 = x (native layout), A_1 = t1, A_2 = u; weights pre-folded.
// Block tile 256 rows (32 nodes x 8 batches) x 64 cols; K=192 in 12 chunks of 16,
// DOUBLE-BUFFERED: LDG chunk i+1 -> regs, compute chunk i, STS -> other buffer,
// one __syncthreads per chunk. LDG latency hides under ~1500cyc of FFMA2.
#define KC    16
#define AST   258            // even (LDS.64 pairs); staging STS conflict-free
__global__ void __launch_bounds__(256, 2) k_gemm2(const float* __restrict__ x,
                                                   const float* __restrict__ bias,
                                                   float* __restrict__ out) {
    __shared__ float As[2][KC * AST];   // 2 x 16512 B
    __shared__ float Ws[2][KC * 64];    // 2 x  4096 B   (total 41216 B)

    int tid = threadIdx.x;
    int tx  = tid & 31;
    int wp  = tid >> 5;              // col group: cols wp*8 .. wp*8+7
    int n0  = blockIdx.x * 32;

    int s_ci = tid & 15;             // staging: k within chunk (0..15)
    int s_b  = (tid >> 4) & 7;       // staging: batch
    int s_h  = tid >> 7;             // staging: dn half (0/1)

    float  a_pref[16];
    float4 w_pref;

    // ---- prefetch helper (reads chunk kc into registers) ----
    auto prefetch = [&](int kc) {
        int t    = kc >> 2;
        int koff = (kc & 3) * KC;
        w_pref = __ldg((const float4*)(g_wt + t * 4096 + koff * 64) + tid);
        if (t == 0) {
            #pragma unroll
            for (int d = 0; d < 16; d++) {
                int n = n0 + s_h * 16 + d;
                if (n >= NN) n = NN - 1;
                a_pref[d] = __ldg(&x[((size_t)s_b * NN + n) * 64 + koff + s_ci]);
            }
        } else {
            const float* src = (t == 1) ? g_t1 : g_u;
            #pragma unroll
            for (int d = 0; d < 16; d++) {
                int n = n0 + s_h * 16 + d;
                if (n >= NN) n = NN - 1;
                a_pref[d] = __ldg(&src[(size_t)n * FF + s_b * 64 + koff + s_ci]);
            }
        }
    };
    auto store_stage = [&](int buf) {
        ((float4*)Ws[buf])[tid] = w_pref;
        #pragma unroll
        for (int d = 0; d < 16; d++) {
            int dn = s_h * 16 + d;
            As[buf][s_ci * AST + dn * 8 + s_b] = a_pref[d];
        }
    };

    unsigned long long acc[4][8];
    #pragma unroll
    for (int i = 0; i < 4; i++)
        #pragma unroll
        for (int j = 0; j < 8; j++) acc[i][j] = 0ULL;

    prefetch(0);
    store_stage(0);
    __syncthreads();

    #pragma unroll 1
    for (int kc = 0; kc < 12; kc++) {
        int cb = kc & 1;
        if (kc < 11) prefetch(kc + 1);     // LDG overlaps compute below

        #pragma unroll 4
        for (int kk = 0; kk < KC; kk++) {
            const float4* wrow = (const float4*)(Ws[cb] + kk * 64 + wp * 8);
            float4 wa = wrow[0], wb = wrow[1];
            unsigned long long wd[8];
            wd[0] = pack2(wa.x); wd[1] = pack2(wa.y);
            wd[2] = pack2(wa.z); wd[3] = pack2(wa.w);
            wd[4] = pack2(wb.x); wd[5] = pack2(wb.y);
            wd[6] = pack2(wb.z); wd[7] = pack2(wb.w);
            #pragma unroll
            for (int jp = 0; jp < 4; jp++) {
                unsigned long long ap =
                    *(const unsigned long long*)(As[cb] + kk * AST + jp * 64 + 2 * tx);
                #pragma unroll
                for (int c = 0; c < 8; c++) FMA2(acc[jp][c], ap, wd[c]);
            }
        }

        if (kc < 11) store_stage(cb ^ 1);  // other buffer; safe vs current compute
        __syncthreads();
    }

    // epilogue: bias + store, rows guarded for the partial last block
    float bvs[8];
    {
        float4 b0 = *(const float4*)(bias + wp * 8);
        float4 b1 = *(const float4*)(bias + wp * 8 + 4);
        bvs[0]=b0.x; bvs[1]=b0.y; bvs[2]=b0.z; bvs[3]=b0.w;
        bvs[4]=b1.x; bvs[5]=b1.y; bvs[6]=b1.z; bvs[7]=b1.w;
    }
    #pragma unroll
    for (int jp = 0; jp < 4; jp++) {
        int m0 = jp * 64 + 2 * tx;       // pair shares dn; batches b and b+1
        int dn = m0 >> 3;
        int n  = n0 + dn;
        if (n >= NN) continue;
        int b  = m0 & 7;
        float lo[8], hi[8];
        #pragma unroll
        for (int c = 0; c < 8; c++) unpack2(acc[jp][c], lo[c], hi[c]);
        float4 o0, o1;
        o0.x = lo[0]+bvs[0]; o0.y = lo[1]+bvs[1]; o0.z = lo[2]+bvs[2]; o0.w = lo[3]+bvs[3];
        o1.x = lo[4]+bvs[4]; o1.y = lo[5]+bvs[5]; o1.z = lo[6]+bvs[6]; o1.w = lo[7]+bvs[7];
        float* p0 = out + ((size_t)b * NN + n) * 64 + wp * 8;
        *(float4*)p0 = o0; *(float4*)(p0 + 4) = o1;
        o0.x = hi[0]+bvs[0]; o0.y = hi[1]+bvs[1]; o0.z = hi[2]+bvs[2]; o0.w = hi[3]+bvs[3];
        o1.x = hi[4]+bvs[4]; o1.y = hi[5]+bvs[5]; o1.z = hi[6]+bvs[6]; o1.w = hi[7]+bvs[7];
        float* p1 = out + ((size_t)(b + 1) * NN + n) * 64 + wp * 8;
        *(float4*)p1 = o0; *(float4*)(p1 + 4) = o1;
    }
}

// ---------------- launch ----------------------------------------------------
extern "C" void kernel_launch(void* const* d_in, const int* in_sizes, int n_in,
                              void* d_out, int out_size) {
    const float* x    = (const float*)d_in[0];   // [8, 50000, 64] f32
    const float* wgt  = (const float*)d_in[1];   // [3, 64, 64]    f32
    const float* bias = (const float*)d_in[2];   // [64]           f32
    const void*  ei   = d_in[3];                 // [2, 400000] int64 or int32
    float* out = (float*)d_out;                  // [8, 50000, 64] f32

    k_setup1<<<(NN + 255) / 256, 256>>>(ei, wgt);
    k_count<<<(EE + 255) / 256, 256>>>(ei);
    k_setup2<<<(NN + 255) / 256, 256>>>();
    k_fill<<<(EE + 255) / 256, 256>>>(ei);
    k_spmm0<<<(NN * 32 + 255) / 256, 256>>>(x);
    k_spmm1<<<(NN * 32 + 255) / 256, 256>>>();
    k_gemm2<<<(NN + 31) / 32, 256>>>(x, bias, out);
}